// round 1
// baseline (speedup 1.0000x reference)
#include <cuda_runtime.h>
#include <math.h>

// Problem constants
#define BATCH 256
#define TSEQ  96
#define PRED  96
#define CIN   321
#define DM    512
#define G4    2048   // 4*DM
#define HD    (BATCH*DM)   // 131072

// ---------------- device scratch (static globals; no runtime alloc) -----------
__device__ float g_mean[BATCH*CIN];
__device__ float g_std [BATCH*CIN];
__device__ float g_istd[BATCH*CIN];
__device__ float g_Gx  [BATCH*TSEQ*G4];     // 201 MB: x_t @ Wih^T for all enc steps
__device__ float g_Wd  [G4*DM];             // Whh + Wih@Wp
__device__ float g_bd  [G4];
__device__ float g_benc[G4];
__device__ float g_h   [2*HD];              // ping-pong hidden state
__device__ float g_c   [HD];
__device__ float g_Hdec[PRED*HD];           // decoder-input hidden states

// ---------------- f32x2 packed-FMA helpers (Blackwell) ------------------------
__device__ __forceinline__ unsigned long long dup2(float x) {
    unsigned long long r;
    asm("mov.b64 %0, {%1, %2};" : "=l"(r) : "f"(x), "f"(x));
    return r;
}
__device__ __forceinline__ void fma2(unsigned long long& d, unsigned long long a, unsigned long long b) {
    asm("fma.rn.f32x2 %0, %1, %2, %0;" : "+l"(d) : "l"(a), "l"(b));
}
__device__ __forceinline__ float lo32(unsigned long long v) { return __uint_as_float((unsigned)v); }
__device__ __forceinline__ float hi32(unsigned long long v) { return __uint_as_float((unsigned)(v >> 32)); }
__device__ __forceinline__ float sigf(float x) { return 1.f / (1.f + expf(-x)); }

// ---------------- stats: mean/std over time per (b, ch) -----------------------
__global__ __launch_bounds__(256) void stats_kernel(const float* __restrict__ x) {
    int idx = blockIdx.x * 256 + threadIdx.x;          // 256*321 threads exactly
    if (idx >= BATCH * CIN) return;
    int b = idx / CIN, ch = idx % CIN;
    float s = 0.f, ss = 0.f;
    const float* p = x + (long)b * TSEQ * CIN + ch;
    #pragma unroll 4
    for (int t = 0; t < TSEQ; t++) { float v = p[t * CIN]; s += v; ss += v * v; }
    float mean = s * (1.f / TSEQ);
    float var = ss * (1.f / TSEQ) - mean * mean;
    if (var < 0.f) var = 0.f;
    float sd = sqrtf(var + 1e-5f);
    g_mean[idx] = mean; g_std[idx] = sd; g_istd[idx] = 1.f / sd;
}

// ---------------- bias fold: benc = bih+bhh ; bd = benc + Wih@bp --------------
__global__ __launch_bounds__(256) void bias_kernel(const float* __restrict__ bih,
                                                   const float* __restrict__ bhh,
                                                   const float* __restrict__ Wih,
                                                   const float* __restrict__ bp) {
    int n = blockIdx.x * 256 + threadIdx.x;
    if (n >= G4) return;
    float be = bih[n] + bhh[n];
    float s = 0.f;
    const float* w = Wih + (long)n * CIN;
    for (int j = 0; j < CIN; j++) s += w[j] * bp[j];
    g_benc[n] = be;
    g_bd[n] = be + s;
}

// ---------------- Wd = Whh + Wih @ Wp  (2048x512, K=321), plain fp32 ----------
__global__ __launch_bounds__(256) void wd_kernel(const float* __restrict__ Wih,
                                                 const float* __restrict__ Wp,
                                                 const float* __restrict__ Whh) {
    __shared__ float As[64 * 17];   // [m][j]
    __shared__ float Bs[16 * 65];   // [j][n]
    int tid = threadIdx.x;
    int n0 = blockIdx.x * 64;       // k-dim of Wd (0..511)
    int m0 = blockIdx.y * 64;       // n-dim (rows of Wih, 0..2047)
    int tr = tid >> 4, tc = tid & 15;
    float acc[4][4] = {};
    for (int j0 = 0; j0 < CIN; j0 += 16) {
        #pragma unroll
        for (int i = 0; i < 4; i++) {
            int l = tid + 256 * i;
            int mr = l >> 4, jj = l & 15;
            int j = j0 + jj;
            As[mr * 17 + jj] = (j < CIN) ? Wih[(long)(m0 + mr) * CIN + j] : 0.f;
        }
        #pragma unroll
        for (int i = 0; i < 4; i++) {
            int l = tid + 256 * i;
            int jj = l >> 6, nr = l & 63;
            int j = j0 + jj;
            Bs[jj * 65 + nr] = (j < CIN) ? Wp[(long)j * DM + n0 + nr] : 0.f;
        }
        __syncthreads();
        #pragma unroll
        for (int jj = 0; jj < 16; jj++) {
            float a[4], bb[4];
            #pragma unroll
            for (int r = 0; r < 4; r++) a[r] = As[(tr * 4 + r) * 17 + jj];
            #pragma unroll
            for (int cc = 0; cc < 4; cc++) bb[cc] = Bs[jj * 65 + tc * 4 + cc];
            #pragma unroll
            for (int r = 0; r < 4; r++)
                #pragma unroll
                for (int cc = 0; cc < 4; cc++) acc[r][cc] += a[r] * bb[cc];
        }
        __syncthreads();
    }
    #pragma unroll
    for (int r = 0; r < 4; r++) {
        int m = m0 + tr * 4 + r;
        #pragma unroll
        for (int cc = 0; cc < 4; cc++) {
            int n = n0 + tc * 4 + cc;
            g_Wd[(long)m * DM + n] = Whh[(long)m * DM + n] + acc[r][cc];
        }
    }
}

// ---------------- Gx = normalize(x) @ Wih^T  (24576 x 2048, K=321) ------------
// A[m,k] = (x[m*321+k]-mean[b,k])*istd[b,k], m = b*96+t. f32x2 micro-kernel.
__global__ __launch_bounds__(256) void gx_kernel(const float* __restrict__ x,
                                                 const float* __restrict__ Wih) {
    __shared__ float As[64 * 17];   // [m][k]
    __shared__ float Bs[16 * 66];   // [k][n] transposed, even pad
    int tid = threadIdx.x;
    int n0 = blockIdx.x * 64;       // 32 tiles
    int m0 = blockIdx.y * 64;       // 384 tiles
    int tr = tid >> 4, tc = tid & 15;
    unsigned long long acc[4][2] = {};
    for (int k0 = 0; k0 < CIN; k0 += 16) {
        #pragma unroll
        for (int i = 0; i < 4; i++) {
            int l = tid + 256 * i;
            int mr = l >> 4, kk = l & 15;
            int k = k0 + kk;
            int m = m0 + mr;
            float v = 0.f;
            if (k < CIN) {
                int b = m / TSEQ;
                int bc = b * CIN + k;
                v = (x[(long)m * CIN + k] - g_mean[bc]) * g_istd[bc];
            }
            As[mr * 17 + kk] = v;
        }
        #pragma unroll
        for (int i = 0; i < 4; i++) {
            int l = tid + 256 * i;
            int nr = l >> 4, kk = l & 15;
            int k = k0 + kk;
            Bs[kk * 66 + nr] = (k < CIN) ? Wih[(long)(n0 + nr) * CIN + k] : 0.f;
        }
        __syncthreads();
        #pragma unroll
        for (int kk = 0; kk < 16; kk++) {
            unsigned long long a[4];
            #pragma unroll
            for (int r = 0; r < 4; r++) a[r] = dup2(As[(tr * 4 + r) * 17 + kk]);
            const unsigned long long* wrow =
                reinterpret_cast<const unsigned long long*>(&Bs[kk * 66 + tc * 4]);
            unsigned long long w0 = wrow[0], w1 = wrow[1];
            #pragma unroll
            for (int r = 0; r < 4; r++) { fma2(acc[r][0], a[r], w0); fma2(acc[r][1], a[r], w1); }
        }
        __syncthreads();
    }
    #pragma unroll
    for (int r = 0; r < 4; r++) {
        int m = m0 + tr * 4 + r;
        float* dst = g_Gx + (long)m * G4 + n0 + tc * 4;
        dst[0] = lo32(acc[r][0]); dst[1] = hi32(acc[r][0]);
        dst[2] = lo32(acc[r][1]); dst[3] = hi32(acc[r][1]);
    }
}

// ---------------- LSTM step: g = h@W^T + pre + bias; gates; update h,c --------
// Block tile: 32 batch rows x (4 gates x 32 j). Grid (8, 16). 256 threads.
__global__ __launch_bounds__(256) void step_kernel(const float* __restrict__ hin,
                                                   float* __restrict__ hout,
                                                   float* __restrict__ cst,
                                                   const float* __restrict__ W,     // [2048][512]
                                                   const float* __restrict__ pre,   // nullable
                                                   long preStride,
                                                   const float* __restrict__ bias,  // [2048]
                                                   float* __restrict__ hstore) {    // nullable
    __shared__ float sm[32 * 33 + 32 * 130];   // hs | ws ; reused as gsh[32][132]
    float* hs = sm;                // [32][33]
    float* ws = sm + 32 * 33;      // [kk][ncol], pad 130 (even)
    int tid = threadIdx.x;
    int b0 = blockIdx.x * 32;
    int j0 = blockIdx.y * 32;
    int tr = tid >> 5;             // warp id 0..7
    int tc = tid & 31;
    unsigned long long acc[4][2] = {};   // rows tr*4+r, cols tc*4 + {0,1},{2,3}

    for (int k0 = 0; k0 < DM; k0 += 32) {
        #pragma unroll
        for (int i = 0; i < 4; i++) {
            int l = tid + 256 * i;
            int row = l >> 5, kk = l & 31;
            hs[row * 33 + kk] = hin[(b0 + row) * DM + k0 + kk];
        }
        #pragma unroll
        for (int i = 0; i < 16; i++) {
            int ncol = tr + 8 * i;                 // 0..127, each once
            int gate = ncol >> 5, jj = ncol & 31;
            int ng = gate * DM + j0 + jj;
            ws[tc * 130 + ncol] = W[(long)ng * DM + k0 + tc];
        }
        __syncthreads();
        #pragma unroll
        for (int kk = 0; kk < 32; kk++) {
            unsigned long long a[4];
            #pragma unroll
            for (int r = 0; r < 4; r++) a[r] = dup2(hs[(tr * 4 + r) * 33 + kk]);
            const unsigned long long* wrow =
                reinterpret_cast<const unsigned long long*>(&ws[kk * 130 + tc * 4]);
            unsigned long long w0 = wrow[0], w1 = wrow[1];
            #pragma unroll
            for (int r = 0; r < 4; r++) { fma2(acc[r][0], a[r], w0); fma2(acc[r][1], a[r], w1); }
        }
        __syncthreads();
    }

    // epilogue phase 1: add pre + bias, stage g tile to smem
    float* gsh = sm;   // [32][132]
    #pragma unroll
    for (int r = 0; r < 4; r++) {
        int row = tr * 4 + r;
        int bglob = b0 + row;
        #pragma unroll
        for (int p = 0; p < 2; p++) {
            float v0 = lo32(acc[r][p]), v1 = hi32(acc[r][p]);
            int c0 = tc * 4 + 2 * p;
            int g0 = c0 >> 5, g1 = (c0 + 1) >> 5;
            int n0g = g0 * DM + j0 + (c0 & 31);
            int n1g = g1 * DM + j0 + ((c0 + 1) & 31);
            float a0 = bias[n0g], a1 = bias[n1g];
            if (pre) {
                a0 += pre[(long)bglob * preStride + n0g];
                a1 += pre[(long)bglob * preStride + n1g];
            }
            gsh[row * 132 + c0] = v0 + a0;
            gsh[row * 132 + c0 + 1] = v1 + a1;
        }
    }
    __syncthreads();

    // epilogue phase 2: gate math, update c/h
    #pragma unroll
    for (int i = 0; i < 4; i++) {
        int cell = tid + 256 * i;
        int row = cell >> 5, jj = cell & 31;
        float iv = gsh[row * 132 + jj];
        float fv = gsh[row * 132 + 32 + jj];
        float gv = gsh[row * 132 + 64 + jj];
        float ov = gsh[row * 132 + 96 + jj];
        int idx = (b0 + row) * DM + j0 + jj;
        float co = cst[idx];
        float cn = sigf(fv) * co + sigf(iv) * tanhf(gv);
        float hn = sigf(ov) * tanhf(cn);
        cst[idx] = cn;
        hout[idx] = hn;
        if (hstore) hstore[idx] = hn;
    }
}

// ---------------- init h, c to zero ------------------------------------------
__global__ __launch_bounds__(256) void init_kernel() {
    int i = blockIdx.x * 256 + threadIdx.x;
    if (i < HD) { g_h[i] = 0.f; g_c[i] = 0.f; }
}

// ---------------- out: Y = Hdec @ Wp^T + bp, denormalize, scatter -------------
// A = g_Hdec (24576 x 512), m = t*256 + b. N = 321.
__global__ __launch_bounds__(256) void out_kernel(const float* __restrict__ Wp,
                                                  const float* __restrict__ bp,
                                                  float* __restrict__ out) {
    __shared__ float As[64 * 17];
    __shared__ float Bs[16 * 66];
    int tid = threadIdx.x;
    int n0 = blockIdx.x * 64;    // 6 tiles (guard n<321)
    int m0 = blockIdx.y * 64;    // 384 tiles
    int tr = tid >> 4, tc = tid & 15;
    unsigned long long acc[4][2] = {};
    for (int k0 = 0; k0 < DM; k0 += 16) {
        #pragma unroll
        for (int i = 0; i < 4; i++) {
            int l = tid + 256 * i;
            int mr = l >> 4, kk = l & 15;
            As[mr * 17 + kk] = g_Hdec[(long)(m0 + mr) * DM + k0 + kk];
        }
        #pragma unroll
        for (int i = 0; i < 4; i++) {
            int l = tid + 256 * i;
            int nr = l >> 4, kk = l & 15;
            int n = n0 + nr;
            Bs[kk * 66 + nr] = (n < CIN) ? Wp[(long)n * DM + k0 + kk] : 0.f;
        }
        __syncthreads();
        #pragma unroll
        for (int kk = 0; kk < 16; kk++) {
            unsigned long long a[4];
            #pragma unroll
            for (int r = 0; r < 4; r++) a[r] = dup2(As[(tr * 4 + r) * 17 + kk]);
            const unsigned long long* wrow =
                reinterpret_cast<const unsigned long long*>(&Bs[kk * 66 + tc * 4]);
            unsigned long long w0 = wrow[0], w1 = wrow[1];
            #pragma unroll
            for (int r = 0; r < 4; r++) { fma2(acc[r][0], a[r], w0); fma2(acc[r][1], a[r], w1); }
        }
        __syncthreads();
    }
    #pragma unroll
    for (int r = 0; r < 4; r++) {
        int m = m0 + tr * 4 + r;
        int t = m >> 8, b = m & 255;
        float vals[4] = { lo32(acc[r][0]), hi32(acc[r][0]), lo32(acc[r][1]), hi32(acc[r][1]) };
        #pragma unroll
        for (int cc = 0; cc < 4; cc++) {
            int n = n0 + tc * 4 + cc;
            if (n < CIN) {
                int bc = b * CIN + n;
                out[(long)b * PRED * CIN + (long)t * CIN + n] =
                    (vals[cc] + bp[n]) * g_std[bc] + g_mean[bc];
            }
        }
    }
}

// ---------------- host launcher ----------------------------------------------
extern "C" void kernel_launch(void* const* d_in, const int* in_sizes, int n_in,
                              void* d_out, int out_size) {
    const float* x   = (const float*)d_in[0];
    const float* Wih = (const float*)d_in[1];
    const float* Whh = (const float*)d_in[2];
    const float* bih = (const float*)d_in[3];
    const float* bhh = (const float*)d_in[4];
    const float* Wp  = (const float*)d_in[5];
    const float* bp  = (const float*)d_in[6];
    float* out = (float*)d_out;

    float *hbuf, *cbuf, *gx, *wd, *bd, *benc, *hdec;
    cudaGetSymbolAddress((void**)&hbuf, g_h);
    cudaGetSymbolAddress((void**)&cbuf, g_c);
    cudaGetSymbolAddress((void**)&gx,   g_Gx);
    cudaGetSymbolAddress((void**)&wd,   g_Wd);
    cudaGetSymbolAddress((void**)&bd,   g_bd);
    cudaGetSymbolAddress((void**)&benc, g_benc);
    cudaGetSymbolAddress((void**)&hdec, g_Hdec);

    stats_kernel<<<(BATCH * CIN + 255) / 256, 256>>>(x);
    bias_kernel<<<(G4 + 255) / 256, 256>>>(bih, bhh, Wih, bp);
    wd_kernel<<<dim3(DM / 64, G4 / 64), 256>>>(Wih, Wp, Whh);
    gx_kernel<<<dim3(G4 / 64, (BATCH * TSEQ) / 64), 256>>>(x, Wih);
    init_kernel<<<HD / 256, 256>>>();

    // 96 encoder updates + 95 decoder updates; outputs y_d = proj(h entering dec step d)
    for (int s = 0; s < TSEQ + PRED - 1; s++) {
        const float* hin = hbuf + (s & 1) * HD;
        float* hout = hbuf + ((s + 1) & 1) * HD;
        bool enc = (s < TSEQ);
        const float* W    = enc ? Whh : wd;
        const float* pre  = enc ? (gx + (long)s * G4) : nullptr;
        long stride       = enc ? (long)TSEQ * G4 : 0;
        const float* bias = enc ? benc : bd;
        float* hst = (s >= TSEQ - 1) ? (hdec + (long)(s - (TSEQ - 1)) * HD) : nullptr;
        step_kernel<<<dim3(BATCH / 32, DM / 32), 256>>>(hin, hout, cbuf, W, pre, stride, bias, hst);
    }

    out_kernel<<<dim3(6, (PRED * BATCH) / 64), 256>>>(Wp, bp, out);
    (void)in_sizes; (void)n_in; (void)out_size;
}